// round 15
// baseline (speedup 1.0000x reference)
#include <cuda_runtime.h>
#include <cuda_fp16.h>
#include <stdint.h>
#include <math.h>

#define D      64
#define CAP    128           // max in-degree slots (Poisson(32): P(>=128) ~ e^-81)
#define MAXN   100000
#define MAXB   1024

// ---------------- static device scratch ----------------
__device__ __half2 g_h0[(MAXN + 1) * 32];  // fp16 node features (scaled by dinv), ping
__device__ __half2 g_h1[(MAXN + 1) * 32];  // pong
__device__ int     g_cnt[MAXN];
__device__ int     g_csr_row[MAXN * CAP];
__device__ float   g_dinv[MAXN];
__device__ int     g_start[MAXB];
__device__ int     g_gcnt[MAXB];
__device__ float   g_hl[MAXB * D];
__device__ float   g_cl[MAXB * D];
__device__ float   g_qstar[MAXB * 2 * D];
__device__ float   g_wT[192 * 256];       // transposed [Wih|Whh]: wT[k][out]
__device__ float   g_bsum[256];           // bih + bhh
__device__ __half  g_wc16[64 * 64];       // Wc in fp16, row-major [k][n]

__device__ __forceinline__ float sigmoidf(float x) { return 1.0f / (1.0f + expf(-x)); }

#define LDSM_X4(r0,r1,r2,r3, addr) \
  asm volatile("ldmatrix.sync.aligned.m8n8.x4.shared.b16 {%0,%1,%2,%3}, [%4];" \
    : "=r"(r0), "=r"(r1), "=r"(r2), "=r"(r3) : "r"(addr))

#define LDSM_X4_T(r0,r1,r2,r3, addr) \
  asm volatile("ldmatrix.sync.aligned.m8n8.x4.trans.shared.b16 {%0,%1,%2,%3}, [%4];" \
    : "=r"(r0), "=r"(r1), "=r"(r2), "=r"(r3) : "r"(addr))

#define MMA16816(c0,c1,c2,c3, a0,a1,a2,a3, b0,b1) \
  asm volatile("mma.sync.aligned.m16n8k16.row.col.f32.f16.f16.f32 " \
    "{%0,%1,%2,%3}, {%4,%5,%6,%7}, {%8,%9}, {%0,%1,%2,%3};" \
    : "+f"(c0), "+f"(c1), "+f"(c2), "+f"(c3) \
    : "r"(a0), "r"(a1), "r"(a2), "r"(a3), "r"(b0), "r"(b1))

// ---------------- init / build ----------------
// zero state + pad row + Wc fp16 conversion (folded)
__global__ void k_zero(int N, int B, const float* __restrict__ Wc) {
    int i = blockIdx.x * blockDim.x + threadIdx.x;
    if (i < N) g_cnt[i] = 0;
    if (i < B) { g_start[i] = N; g_gcnt[i] = 0; }
    if (i < B * D) { g_hl[i] = 0.f; g_cl[i] = 0.f; }
    if (i < B * 2 * D) g_qstar[i] = 0.f;
    if (i < 64 * 64) g_wc16[i] = __float2half(Wc[i]);
    if (i < 32) {
        __half2 z = __floats2half2_rn(0.f, 0.f);
        g_h0[MAXN * 32 + i] = z;
        g_h1[MAXN * 32 + i] = z;
    }
}

__global__ void k_build(const int* __restrict__ ei, int E) {
    int e = blockIdx.x * blockDim.x + threadIdx.x;
    if (e >= E) return;
    int r = ei[e];
    int c = ei[E + e];
    int slot = atomicAdd(&g_cnt[c], 1);
    if (slot < CAP) g_csr_row[c * CAP + slot] = r;
}

// merged: dinv + graph boundaries/counts + LSTM weight transpose
// (runs after k_build so g_cnt is final; before k_init_feat which reads g_dinv)
__global__ void k_s2sprep(const int* __restrict__ batch, int N,
                          const float* __restrict__ Wih, const float* __restrict__ Whh,
                          const float* __restrict__ bih, const float* __restrict__ bhh) {
    int i = blockIdx.x * blockDim.x + threadIdx.x;
    if (i < N) {
        float deg = (float)(g_cnt[i] + 1);
        g_dinv[i] = rsqrtf(deg);
        int bn = batch[i];
        if (i == 0 || batch[i - 1] != bn) g_start[bn] = i;
        atomicAdd(&g_gcnt[bn], 1);
    }
    if (i < 192 * 256) {
        int k = i >> 8, o = i & 255;
        float v = (k < 128) ? Wih[o * 128 + k] : Whh[o * 64 + (k - 128)];
        g_wT[k * 256 + o] = v;
        if (k == 0) g_bsum[o] = bih[o] + bhh[o];
    }
}

// out0 = dinv * relu(x @ W0 + b0) -> fp16 ping buffer (pre-scaled storage)
__global__ void k_init_feat(const float* __restrict__ x, const float* __restrict__ W0,
                            const float* __restrict__ b0, int N) {
    int idx = blockIdx.x * blockDim.x + threadIdx.x;
    if (idx >= N * 32) return;
    int n = idx >> 5, p = idx & 31;
    int c0 = 2 * p;
    float a0 = b0[c0], a1 = b0[c0 + 1];
    const float* xr = x + n * 15;
#pragma unroll
    for (int k = 0; k < 15; k++) {
        float xv = xr[k];
        a0 += xv * W0[k * D + c0];
        a1 += xv * W0[k * D + c0 + 1];
    }
    float dv = g_dinv[n];
    g_h0[idx] = __floats2half2_rn(dv * fmaxf(a0, 0.f), dv * fmaxf(a1, 0.f));
}

// ---------------- fused propagation: gather(fp16) -> HMMA GEMM -> fp16 ----
// features pre-scaled: f = dinv*out ; agg = sum f_r + f_self ; x = dinv*agg
// out = relu(x @ Wc + bc) ; store last ? out : dinv*out
__global__ void k_prop(const float* __restrict__ bc, int N, int flip, int last) {
    const __half2* __restrict__ src = flip ? g_h1 : g_h0;
    __half2*       __restrict__ dst = flip ? g_h0 : g_h1;
    __shared__ __half xs_h[64][72];    // gathered x tile (fp16), ldmatrix-friendly
    __shared__ __half ws_h[64][72];    // Wc fp16 [k][n]
    __shared__ float  bcs[64];
    int t = threadIdx.x;               // 256 threads
    int base = blockIdx.x * 64;
    int wrp = t >> 5, lane = t & 31;

    if (t < 64) bcs[t] = bc[t];
    {
        const uint4* wsrc = (const uint4*)g_wc16;
#pragma unroll
        for (int i = t; i < 512; i += 256) {
            int row = i >> 3, c8 = (i & 7) << 3;
            *(uint4*)&ws_h[row][c8] = wsrc[i];
        }
    }

    // gather: warp wrp handles local rows wrp*8 .. wrp*8+7
    // 16-wide main loop (NO padding), remainders 8/4/scalar
#pragma unroll 1
    for (int q = 0; q < 8; q++) {
        int row = wrp * 8 + q;
        int n = base + row;
        float ax = 0.f, ay = 0.f;
        if (n < N) {
            int cnt = g_cnt[n]; if (cnt > CAP) cnt = CAP;
            const int* rows = &g_csr_row[n * CAP];
            int s16 = cnt & ~15;
            if (s16) {
                const int4* ip = (const int4*)rows;
                int4 i0 = ip[0], i1 = ip[1], i2 = ip[2], i3 = ip[3];
                for (int s = 16; ; s += 16, ip += 4) {
                    int4 j0, j1, j2, j3;
                    if (s < s16) { j0 = ip[4]; j1 = ip[5]; j2 = ip[6]; j3 = ip[7]; }
                    __half2 h0  = src[i0.x * 32 + lane];
                    __half2 h1  = src[i0.y * 32 + lane];
                    __half2 h2  = src[i0.z * 32 + lane];
                    __half2 h3  = src[i0.w * 32 + lane];
                    __half2 h4  = src[i1.x * 32 + lane];
                    __half2 h5  = src[i1.y * 32 + lane];
                    __half2 h6  = src[i1.z * 32 + lane];
                    __half2 h7  = src[i1.w * 32 + lane];
                    __half2 h8  = src[i2.x * 32 + lane];
                    __half2 h9  = src[i2.y * 32 + lane];
                    __half2 h10 = src[i2.z * 32 + lane];
                    __half2 h11 = src[i2.w * 32 + lane];
                    __half2 h12 = src[i3.x * 32 + lane];
                    __half2 h13 = src[i3.y * 32 + lane];
                    __half2 h14 = src[i3.z * 32 + lane];
                    __half2 h15 = src[i3.w * 32 + lane];
                    __half2 t0 = __hadd2(h0,  h1);
                    __half2 t1 = __hadd2(h2,  h3);
                    __half2 t2 = __hadd2(h4,  h5);
                    __half2 t3 = __hadd2(h6,  h7);
                    __half2 t4 = __hadd2(h8,  h9);
                    __half2 t5 = __hadd2(h10, h11);
                    __half2 t6 = __hadd2(h12, h13);
                    __half2 t7 = __hadd2(h14, h15);
                    t0 = __hadd2(t0, t1);
                    t2 = __hadd2(t2, t3);
                    t4 = __hadd2(t4, t5);
                    t6 = __hadd2(t6, t7);
                    t0 = __hadd2(t0, t2);
                    t4 = __hadd2(t4, t6);
                    t0 = __hadd2(t0, t4);
                    float2 f = __half22float2(t0);
                    ax += f.x; ay += f.y;
                    if (s >= s16) break;
                    i0 = j0; i1 = j1; i2 = j2; i3 = j3;
                }
            }
            int s = s16;
            if (s + 8 <= cnt) {
                int4 ra = *(const int4*)(rows + s);
                int4 rb = *(const int4*)(rows + s + 4);
                __half2 h0 = src[ra.x * 32 + lane];
                __half2 h1 = src[ra.y * 32 + lane];
                __half2 h2 = src[ra.z * 32 + lane];
                __half2 h3 = src[ra.w * 32 + lane];
                __half2 h4 = src[rb.x * 32 + lane];
                __half2 h5 = src[rb.y * 32 + lane];
                __half2 h6 = src[rb.z * 32 + lane];
                __half2 h7 = src[rb.w * 32 + lane];
                __half2 t0 = __hadd2(__hadd2(h0, h1), __hadd2(h2, h3));
                __half2 t2 = __hadd2(__hadd2(h4, h5), __hadd2(h6, h7));
                t0 = __hadd2(t0, t2);
                float2 f = __half22float2(t0);
                ax += f.x; ay += f.y;
                s += 8;
            }
            if (s + 4 <= cnt) {
                int4 ra = *(const int4*)(rows + s);
                __half2 h0 = src[ra.x * 32 + lane];
                __half2 h1 = src[ra.y * 32 + lane];
                __half2 h2 = src[ra.z * 32 + lane];
                __half2 h3 = src[ra.w * 32 + lane];
                __half2 t0 = __hadd2(__hadd2(h0, h1), __hadd2(h2, h3));
                float2 f = __half22float2(t0);
                ax += f.x; ay += f.y;
                s += 4;
            }
            for (; s < cnt; s++) {
                float2 f = __half22float2(src[rows[s] * 32 + lane]);
                ax += f.x; ay += f.y;
            }
            float2 hs = __half22float2(src[n * 32 + lane]);
            float dv = g_dinv[n];
            ax = dv * (ax + hs.x);
            ay = dv * (ay + hs.y);
        }
        *(__half2*)&xs_h[row][lane * 2] = __floats2half2_rn(ax, ay);
    }
    __syncthreads();

    // ---- HMMA GEMM: C(64x64) = xs_h @ ws_h, warp tile 16x32 ----
    int wr = wrp >> 1;
    int wc = wrp & 1;
    int g  = lane >> 2;
    int tt = lane & 3;

    float c[4][4];
#pragma unroll
    for (int i = 0; i < 4; i++)
#pragma unroll
        for (int j = 0; j < 4; j++) c[i][j] = 0.f;

    int arow = wr * 16 + ((lane >> 3) & 1) * 8 + (lane & 7);
    int asub = (lane >> 4) * 8;
    int brsub = ((lane >> 3) & 1) * 8 + (lane & 7);
    int bcsub = (lane >> 4) * 8;

#pragma unroll
    for (int kk = 0; kk < 4; kk++) {
        uint32_t a0, a1, a2, a3;
        uint32_t aaddr = (uint32_t)__cvta_generic_to_shared(&xs_h[arow][kk * 16 + asub]);
        LDSM_X4(a0, a1, a2, a3, aaddr);
#pragma unroll
        for (int hn = 0; hn < 2; hn++) {
            uint32_t bb0, bb1, bb2, bb3;
            uint32_t baddr = (uint32_t)__cvta_generic_to_shared(
                &ws_h[kk * 16 + brsub][wc * 32 + hn * 16 + bcsub]);
            LDSM_X4_T(bb0, bb1, bb2, bb3, baddr);
            MMA16816(c[hn*2][0], c[hn*2][1], c[hn*2][2], c[hn*2][3],
                     a0, a1, a2, a3, bb0, bb1);
            MMA16816(c[hn*2+1][0], c[hn*2+1][1], c[hn*2+1][2], c[hn*2+1][3],
                     a0, a1, a2, a3, bb2, bb3);
        }
    }

    // ---- epilogue: bias + relu + scale + fp16 store ----
    int r0 = base + wr * 16 + g;
    int r1 = r0 + 8;
    float sc0 = 1.f, sc1 = 1.f;
    if (!last) {
        if (r0 < N) sc0 = g_dinv[r0];
        if (r1 < N) sc1 = g_dinv[r1];
    }
#pragma unroll
    for (int ns = 0; ns < 4; ns++) {
        int col = wc * 32 + ns * 8 + 2 * tt;
        float bx = bcs[col], by = bcs[col + 1];
        if (r0 < N) {
            float vx = fmaxf(c[ns][0] + bx, 0.f) * sc0;
            float vy = fmaxf(c[ns][1] + by, 0.f) * sc0;
            dst[(size_t)r0 * 32 + (col >> 1)] = __floats2half2_rn(vx, vy);
        }
        if (r1 < N) {
            float vx = fmaxf(c[ns][2] + bx, 0.f) * sc1;
            float vy = fmaxf(c[ns][3] + by, 0.f) * sc1;
            dst[(size_t)r1 * 32 + (col >> 1)] = __floats2half2_rn(vx, vy);
        }
    }
}

// ---------------- Set2Set ----------------
// gates GEMM: 8 graphs per block
__global__ void k_gates(int B) {
    int t = threadIdx.x;   // 256
    int gb = blockIdx.x * 8;
    __shared__ float xs[8][193];
    for (int id = t; id < 8 * 192; id += 256) {
        int g = id / 192, k = id % 192;
        int gg = gb + g;
        float v = 0.f;
        if (gg < B) v = (k < 128) ? g_qstar[gg * 128 + k] : g_hl[gg * 64 + (k - 128)];
        xs[g][k] = v;
    }
    __syncthreads();

    float acc[8];
#pragma unroll
    for (int g = 0; g < 8; g++) acc[g] = 0.f;
#pragma unroll 4
    for (int k = 0; k < 192; k++) {
        float wv = g_wT[k * 256 + t];
#pragma unroll
        for (int g = 0; g < 8; g++) acc[g] += xs[g][k] * wv;
    }
    __shared__ float gsh[256][9];
    float bsum = g_bsum[t];
#pragma unroll
    for (int g = 0; g < 8; g++) gsh[t][g] = acc[g] + bsum;
    __syncthreads();

    if (t < 64) {
        int j = t;
        for (int g = 0; g < 8; g++) {
            int gg = gb + g;
            if (gg >= B) break;
            float ig = sigmoidf(gsh[       j][g]);
            float fg = sigmoidf(gsh[ 64 + j][g]);
            float gv = tanhf   (gsh[128 + j][g]);
            float og = sigmoidf(gsh[192 + j][g]);
            int gi = gg * 64 + j;
            float cv = fg * g_cl[gi] + ig * gv;
            g_cl[gi] = cv;
            g_hl[gi] = og * tanhf(cv);
        }
    }
}

// single-pass online-softmax attention
__global__ void k_attn(int N) {
    int b = blockIdx.x, tid = threadIdx.x;
    int wrp = tid >> 5, lane = tid & 31;
    int st = g_start[b];
    int cnt = g_gcnt[b];
    __shared__ float s_m[8], s_ls[8], s_scale[8];
    __shared__ float s_r[8][64];
    __shared__ float inv_s;

    float2 qv = *(const float2*)&g_hl[b * 64 + lane * 2];
    float m_w = -INFINITY, ls_w = 0.f;
    float rx = 0.f, ry = 0.f;
    for (int i = wrp; i < cnt; i += 8) {
        int n = st + i;
        float2 ov = __half22float2(g_h0[(size_t)n * 32 + lane]);
        float s = ov.x * qv.x + ov.y * qv.y;
#pragma unroll
        for (int o = 16; o; o >>= 1) s += __shfl_xor_sync(0xffffffffu, s, o);
        float m_new = fmaxf(m_w, s);
        float scale = expf(m_w - m_new);
        float a = expf(s - m_new);
        ls_w = ls_w * scale + a;
        rx = rx * scale + a * ov.x;
        ry = ry * scale + a * ov.y;
        m_w = m_new;
    }
    s_r[wrp][lane * 2]     = rx;
    s_r[wrp][lane * 2 + 1] = ry;
    if (lane == 0) { s_m[wrp] = m_w; s_ls[wrp] = ls_w; }
    __syncthreads();

    if (tid < 8) {
        float mv = s_m[tid];
        float M = mv;
#pragma unroll
        for (int o = 4; o; o >>= 1) M = fmaxf(M, __shfl_xor_sync(0xffu, M, o));
        float sc = (mv > -INFINITY) ? expf(mv - M) : 0.f;
        s_scale[tid] = sc;
        float l = s_ls[tid] * sc;
#pragma unroll
        for (int o = 4; o; o >>= 1) l += __shfl_xor_sync(0xffu, l, o);
        if (tid == 0) inv_s = (l > 0.f) ? (1.0f / l) : 0.f;
    }
    __syncthreads();

    if (tid < 64) {
        float r = 0.f;
#pragma unroll
        for (int w = 0; w < 8; w++) r += s_scale[w] * s_r[w][tid];
        r *= inv_s;
        g_qstar[b * 128 + tid]      = g_hl[b * 64 + tid];
        g_qstar[b * 128 + 64 + tid] = r;
    }
}

__global__ void k_final(const float* __restrict__ W1, const float* __restrict__ b1,
                        const float* __restrict__ W2, const float* __restrict__ b2,
                        float* __restrict__ y) {
    int b = blockIdx.x, t = threadIdx.x;  // 64 threads
    __shared__ float qs[128];
    __shared__ float hid[64];
    qs[t]      = g_qstar[b * 128 + t];
    qs[t + 64] = g_qstar[b * 128 + 64 + t];
    __syncthreads();
    float acc = b1[t];
#pragma unroll 8
    for (int k = 0; k < 128; k++) acc += qs[k] * W1[k * 64 + t];
    hid[t] = fmaxf(acc, 0.f);
    __syncthreads();
    if (t < 12) {
        float a = b2[t];
#pragma unroll 8
        for (int k = 0; k < 64; k++) a += hid[k] * W2[k * 12 + t];
        y[b * 12 + t] = a;
    }
}

// ---------------- launch ----------------
extern "C" void kernel_launch(void* const* d_in, const int* in_sizes, int n_in,
                              void* d_out, int out_size) {
    const float* x     = (const float*)d_in[0];
    const int*   ei    = (const int*)  d_in[1];
    const int*   batch = (const int*)  d_in[2];
    const float* W0    = (const float*)d_in[3];
    const float* b0    = (const float*)d_in[4];
    const float* Wc    = (const float*)d_in[5];
    const float* bc    = (const float*)d_in[6];
    const float* Wih   = (const float*)d_in[7];
    const float* Whh   = (const float*)d_in[8];
    const float* bih   = (const float*)d_in[9];
    const float* bhh   = (const float*)d_in[10];
    const float* W1    = (const float*)d_in[11];
    const float* b1    = (const float*)d_in[12];
    const float* W2    = (const float*)d_in[13];
    const float* b2    = (const float*)d_in[14];
    float* y = (float*)d_out;

    int N = in_sizes[0] / 15;
    int E = in_sizes[1] / 2;
    int B = out_size / 12;

    // ---- init + build ----
    int zmax = (N > B * 2 * D) ? N : B * 2 * D;
    k_zero<<<(zmax + 255) / 256, 256>>>(N, B, Wc);
    k_build<<<(E + 255) / 256, 256>>>(ei, E);
    k_s2sprep<<<(N + 255) / 256, 256>>>(batch, N, Wih, Whh, bih, bhh);
    k_init_feat<<<(N * 32 + 255) / 256, 256>>>(x, W0, b0, N);

    // ---- 6 fused propagation steps ----
    for (int s = 0; s < 6; s++) {
        k_prop<<<(N + 63) / 64, 256>>>(bc, N, s & 1, (s == 5) ? 1 : 0);
    }

    // ---- Set2Set: 6 x (gates, attn) ----
    for (int s = 0; s < 6; s++) {
        k_gates<<<(B + 7) / 8, 256>>>(B);
        k_attn<<<B, 256>>>(N);
    }

    // ---- final MLP ----
    k_final<<<B, 64>>>(W1, b1, W2, b2, y);
}

// round 16
// speedup vs baseline: 1.1034x; 1.1034x over previous
#include <cuda_runtime.h>
#include <cuda_fp16.h>
#include <stdint.h>
#include <math.h>

#define D      64
#define CAP    128           // max in-degree slots (Poisson(32): P(>=128) ~ e^-81)
#define MAXN   100000
#define MAXB   1024

// ---------------- static device scratch ----------------
__device__ __half2 g_h0[(MAXN + 1) * 32];  // fp16 node features (scaled by dinv), ping
__device__ __half2 g_h1[(MAXN + 1) * 32];  // pong
__device__ int     g_cnt[MAXN];
__device__ int     g_csr_row[MAXN * CAP];
__device__ float   g_dinv[MAXN];
__device__ int     g_start[MAXB];
__device__ int     g_gcnt[MAXB];
__device__ float   g_hl[MAXB * D];
__device__ float   g_cl[MAXB * D];
__device__ float   g_qstar[MAXB * 2 * D];
__device__ float   g_wT[192 * 256];       // transposed [Wih|Whh]: wT[k][out]
__device__ float   g_bsum[256];           // bih + bhh
__device__ __half  g_wc16[64 * 64];       // Wc in fp16, row-major [k][n]

__device__ __forceinline__ float sigmoidf(float x) { return 1.0f / (1.0f + expf(-x)); }

#define LDSM_X4(r0,r1,r2,r3, addr) \
  asm volatile("ldmatrix.sync.aligned.m8n8.x4.shared.b16 {%0,%1,%2,%3}, [%4];" \
    : "=r"(r0), "=r"(r1), "=r"(r2), "=r"(r3) : "r"(addr))

#define LDSM_X4_T(r0,r1,r2,r3, addr) \
  asm volatile("ldmatrix.sync.aligned.m8n8.x4.trans.shared.b16 {%0,%1,%2,%3}, [%4];" \
    : "=r"(r0), "=r"(r1), "=r"(r2), "=r"(r3) : "r"(addr))

#define MMA16816(c0,c1,c2,c3, a0,a1,a2,a3, b0,b1) \
  asm volatile("mma.sync.aligned.m16n8k16.row.col.f32.f16.f16.f32 " \
    "{%0,%1,%2,%3}, {%4,%5,%6,%7}, {%8,%9}, {%0,%1,%2,%3};" \
    : "+f"(c0), "+f"(c1), "+f"(c2), "+f"(c3) \
    : "r"(a0), "r"(a1), "r"(a2), "r"(a3), "r"(b0), "r"(b1))

// ---------------- init / build ----------------
// zero state + pad row + Wc fp16 conversion (folded)
__global__ void k_zero(int N, int B, const float* __restrict__ Wc) {
    int i = blockIdx.x * blockDim.x + threadIdx.x;
    if (i < N) g_cnt[i] = 0;
    if (i < B) { g_start[i] = N; g_gcnt[i] = 0; }
    if (i < B * D) { g_hl[i] = 0.f; g_cl[i] = 0.f; }
    if (i < B * 2 * D) g_qstar[i] = 0.f;
    if (i < 64 * 64) g_wc16[i] = __float2half(Wc[i]);
    if (i < 32) {
        __half2 z = __floats2half2_rn(0.f, 0.f);
        g_h0[MAXN * 32 + i] = z;
        g_h1[MAXN * 32 + i] = z;
    }
}

__global__ void k_build(const int* __restrict__ ei, int E) {
    int e = blockIdx.x * blockDim.x + threadIdx.x;
    if (e >= E) return;
    int r = ei[e];
    int c = ei[E + e];
    int slot = atomicAdd(&g_cnt[c], 1);
    if (slot < CAP) g_csr_row[c * CAP + slot] = r;
}

// merged: dinv + graph boundaries/counts + LSTM weight transpose
__global__ void k_s2sprep(const int* __restrict__ batch, int N,
                          const float* __restrict__ Wih, const float* __restrict__ Whh,
                          const float* __restrict__ bih, const float* __restrict__ bhh) {
    int i = blockIdx.x * blockDim.x + threadIdx.x;
    if (i < N) {
        float deg = (float)(g_cnt[i] + 1);
        g_dinv[i] = rsqrtf(deg);
        int bn = batch[i];
        if (i == 0 || batch[i - 1] != bn) g_start[bn] = i;
        atomicAdd(&g_gcnt[bn], 1);
    }
    if (i < 192 * 256) {
        int k = i >> 8, o = i & 255;
        float v = (k < 128) ? Wih[o * 128 + k] : Whh[o * 64 + (k - 128)];
        g_wT[k * 256 + o] = v;
        if (k == 0) g_bsum[o] = bih[o] + bhh[o];
    }
}

// out0 = dinv * relu(x @ W0 + b0) -> fp16 ping buffer (pre-scaled storage)
// smem-staged W0 + x rows; block = 256 threads = 8 nodes
__global__ void k_init_feat(const float* __restrict__ x, const float* __restrict__ W0,
                            const float* __restrict__ b0, int N) {
    __shared__ float w0s[15][64];
    __shared__ float b0s[64];
    __shared__ float xrs[8][16];   // 8 nodes x 15 features (padded to 16)
    int t = threadIdx.x;
    int nb = blockIdx.x * 8;

    if (t < 64) b0s[t] = b0[t];
    for (int i = t; i < 15 * 64; i += 256) w0s[i >> 6][i & 63] = W0[i];
    // 8 rows x 15 floats = 120 loads
    if (t < 120) {
        int ln = t / 15, lf = t % 15;
        int n = nb + ln;
        xrs[ln][lf] = (n < N) ? x[n * 15 + lf] : 0.f;
    }
    __syncthreads();

    int ln = t >> 5, p = t & 31;   // node ln (0..7), pair p
    int n = nb + ln;
    if (n >= N) return;
    int c0 = 2 * p;
    float a0 = b0s[c0], a1 = b0s[c0 + 1];
#pragma unroll
    for (int k = 0; k < 15; k++) {
        float xv = xrs[ln][k];
        a0 += xv * w0s[k][c0];
        a1 += xv * w0s[k][c0 + 1];
    }
    float dv = g_dinv[n];
    g_h0[(size_t)n * 32 + p] = __floats2half2_rn(dv * fmaxf(a0, 0.f), dv * fmaxf(a1, 0.f));
}

// ---------------- fused propagation: gather(fp16) -> HMMA GEMM -> fp16 ----
// (R14's exact 8-wide form — best measured; width/padding axes falsified)
__global__ void k_prop(const float* __restrict__ bc, int N, int flip, int last) {
    const __half2* __restrict__ src = flip ? g_h1 : g_h0;
    __half2*       __restrict__ dst = flip ? g_h0 : g_h1;
    __shared__ __half xs_h[64][72];
    __shared__ __half ws_h[64][72];
    __shared__ float  bcs[64];
    int t = threadIdx.x;               // 256 threads
    int base = blockIdx.x * 64;
    int wrp = t >> 5, lane = t & 31;

    if (t < 64) bcs[t] = bc[t];
    {
        const uint4* wsrc = (const uint4*)g_wc16;
#pragma unroll
        for (int i = t; i < 512; i += 256) {
            int row = i >> 3, c8 = (i & 7) << 3;
            *(uint4*)&ws_h[row][c8] = wsrc[i];
        }
    }

#pragma unroll 1
    for (int q = 0; q < 8; q++) {
        int row = wrp * 8 + q;
        int n = base + row;
        float ax = 0.f, ay = 0.f;
        if (n < N) {
            int cnt = g_cnt[n]; if (cnt > CAP) cnt = CAP;
            const int* rows = &g_csr_row[n * CAP];
            int s8 = cnt & ~7;
            if (s8) {
                int4 ra = *(const int4*)(rows);
                int4 rb = *(const int4*)(rows + 4);
                for (int s = 8; ; s += 8) {
                    int4 ra_n, rb_n;
                    if (s < s8) {
                        ra_n = *(const int4*)(rows + s);
                        rb_n = *(const int4*)(rows + s + 4);
                    }
                    __half2 h0 = src[ra.x * 32 + lane];
                    __half2 h1 = src[ra.y * 32 + lane];
                    __half2 h2 = src[ra.z * 32 + lane];
                    __half2 h3 = src[ra.w * 32 + lane];
                    __half2 h4 = src[rb.x * 32 + lane];
                    __half2 h5 = src[rb.y * 32 + lane];
                    __half2 h6 = src[rb.z * 32 + lane];
                    __half2 h7 = src[rb.w * 32 + lane];
                    __half2 t0 = __hadd2(h0, h1);
                    __half2 t1 = __hadd2(h2, h3);
                    __half2 t2 = __hadd2(h4, h5);
                    __half2 t3 = __hadd2(h6, h7);
                    t0 = __hadd2(t0, t1);
                    t2 = __hadd2(t2, t3);
                    t0 = __hadd2(t0, t2);
                    float2 f = __half22float2(t0);
                    ax += f.x; ay += f.y;
                    if (s >= s8) break;
                    ra = ra_n; rb = rb_n;
                }
            }
            int s = s8;
            if (s + 4 <= cnt) {
                int4 ra = *(const int4*)(rows + s);
                __half2 h0 = src[ra.x * 32 + lane];
                __half2 h1 = src[ra.y * 32 + lane];
                __half2 h2 = src[ra.z * 32 + lane];
                __half2 h3 = src[ra.w * 32 + lane];
                __half2 t0 = __hadd2(__hadd2(h0, h1), __hadd2(h2, h3));
                float2 f = __half22float2(t0);
                ax += f.x; ay += f.y;
                s += 4;
            }
            for (; s < cnt; s++) {
                float2 f = __half22float2(src[rows[s] * 32 + lane]);
                ax += f.x; ay += f.y;
            }
            float2 hs = __half22float2(src[n * 32 + lane]);
            float dv = g_dinv[n];
            ax = dv * (ax + hs.x);
            ay = dv * (ay + hs.y);
        }
        *(__half2*)&xs_h[row][lane * 2] = __floats2half2_rn(ax, ay);
    }
    __syncthreads();

    // ---- HMMA GEMM: C(64x64) = xs_h @ ws_h, warp tile 16x32 ----
    int wr = wrp >> 1;
    int wc = wrp & 1;
    int g  = lane >> 2;
    int tt = lane & 3;

    float c[4][4];
#pragma unroll
    for (int i = 0; i < 4; i++)
#pragma unroll
        for (int j = 0; j < 4; j++) c[i][j] = 0.f;

    int arow = wr * 16 + ((lane >> 3) & 1) * 8 + (lane & 7);
    int asub = (lane >> 4) * 8;
    int brsub = ((lane >> 3) & 1) * 8 + (lane & 7);
    int bcsub = (lane >> 4) * 8;

#pragma unroll
    for (int kk = 0; kk < 4; kk++) {
        uint32_t a0, a1, a2, a3;
        uint32_t aaddr = (uint32_t)__cvta_generic_to_shared(&xs_h[arow][kk * 16 + asub]);
        LDSM_X4(a0, a1, a2, a3, aaddr);
#pragma unroll
        for (int hn = 0; hn < 2; hn++) {
            uint32_t bb0, bb1, bb2, bb3;
            uint32_t baddr = (uint32_t)__cvta_generic_to_shared(
                &ws_h[kk * 16 + brsub][wc * 32 + hn * 16 + bcsub]);
            LDSM_X4_T(bb0, bb1, bb2, bb3, baddr);
            MMA16816(c[hn*2][0], c[hn*2][1], c[hn*2][2], c[hn*2][3],
                     a0, a1, a2, a3, bb0, bb1);
            MMA16816(c[hn*2+1][0], c[hn*2+1][1], c[hn*2+1][2], c[hn*2+1][3],
                     a0, a1, a2, a3, bb2, bb3);
        }
    }

    // ---- epilogue ----
    int r0 = base + wr * 16 + g;
    int r1 = r0 + 8;
    float sc0 = 1.f, sc1 = 1.f;
    if (!last) {
        if (r0 < N) sc0 = g_dinv[r0];
        if (r1 < N) sc1 = g_dinv[r1];
    }
#pragma unroll
    for (int ns = 0; ns < 4; ns++) {
        int col = wc * 32 + ns * 8 + 2 * tt;
        float bx = bcs[col], by = bcs[col + 1];
        if (r0 < N) {
            float vx = fmaxf(c[ns][0] + bx, 0.f) * sc0;
            float vy = fmaxf(c[ns][1] + by, 0.f) * sc0;
            dst[(size_t)r0 * 32 + (col >> 1)] = __floats2half2_rn(vx, vy);
        }
        if (r1 < N) {
            float vx = fmaxf(c[ns][2] + bx, 0.f) * sc1;
            float vy = fmaxf(c[ns][3] + by, 0.f) * sc1;
            dst[(size_t)r1 * 32 + (col >> 1)] = __floats2half2_rn(vx, vy);
        }
    }
}

// ---------------- Set2Set ----------------
__global__ void k_gates(int B) {
    int t = threadIdx.x;   // 256
    int gb = blockIdx.x * 8;
    __shared__ float xs[8][193];
    for (int id = t; id < 8 * 192; id += 256) {
        int g = id / 192, k = id % 192;
        int gg = gb + g;
        float v = 0.f;
        if (gg < B) v = (k < 128) ? g_qstar[gg * 128 + k] : g_hl[gg * 64 + (k - 128)];
        xs[g][k] = v;
    }
    __syncthreads();

    float acc[8];
#pragma unroll
    for (int g = 0; g < 8; g++) acc[g] = 0.f;
#pragma unroll 4
    for (int k = 0; k < 192; k++) {
        float wv = g_wT[k * 256 + t];
#pragma unroll
        for (int g = 0; g < 8; g++) acc[g] += xs[g][k] * wv;
    }
    __shared__ float gsh[256][9];
    float bsum = g_bsum[t];
#pragma unroll
    for (int g = 0; g < 8; g++) gsh[t][g] = acc[g] + bsum;
    __syncthreads();

    if (t < 64) {
        int j = t;
        for (int g = 0; g < 8; g++) {
            int gg = gb + g;
            if (gg >= B) break;
            float ig = sigmoidf(gsh[       j][g]);
            float fg = sigmoidf(gsh[ 64 + j][g]);
            float gv = tanhf   (gsh[128 + j][g]);
            float og = sigmoidf(gsh[192 + j][g]);
            int gi = gg * 64 + j;
            float cv = fg * g_cl[gi] + ig * gv;
            g_cl[gi] = cv;
            g_hl[gi] = og * tanhf(cv);
        }
    }
}

// single-pass online-softmax attention
__global__ void k_attn(int N) {
    int b = blockIdx.x, tid = threadIdx.x;
    int wrp = tid >> 5, lane = tid & 31;
    int st = g_start[b];
    int cnt = g_gcnt[b];
    __shared__ float s_m[8], s_ls[8], s_scale[8];
    __shared__ float s_r[8][64];
    __shared__ float inv_s;

    float2 qv = *(const float2*)&g_hl[b * 64 + lane * 2];
    float m_w = -INFINITY, ls_w = 0.f;
    float rx = 0.f, ry = 0.f;
    for (int i = wrp; i < cnt; i += 8) {
        int n = st + i;
        float2 ov = __half22float2(g_h0[(size_t)n * 32 + lane]);
        float s = ov.x * qv.x + ov.y * qv.y;
#pragma unroll
        for (int o = 16; o; o >>= 1) s += __shfl_xor_sync(0xffffffffu, s, o);
        float m_new = fmaxf(m_w, s);
        float scale = expf(m_w - m_new);
        float a = expf(s - m_new);
        ls_w = ls_w * scale + a;
        rx = rx * scale + a * ov.x;
        ry = ry * scale + a * ov.y;
        m_w = m_new;
    }
    s_r[wrp][lane * 2]     = rx;
    s_r[wrp][lane * 2 + 1] = ry;
    if (lane == 0) { s_m[wrp] = m_w; s_ls[wrp] = ls_w; }
    __syncthreads();

    if (tid < 8) {
        float mv = s_m[tid];
        float M = mv;
#pragma unroll
        for (int o = 4; o; o >>= 1) M = fmaxf(M, __shfl_xor_sync(0xffu, M, o));
        float sc = (mv > -INFINITY) ? expf(mv - M) : 0.f;
        s_scale[tid] = sc;
        float l = s_ls[tid] * sc;
#pragma unroll
        for (int o = 4; o; o >>= 1) l += __shfl_xor_sync(0xffu, l, o);
        if (tid == 0) inv_s = (l > 0.f) ? (1.0f / l) : 0.f;
    }
    __syncthreads();

    if (tid < 64) {
        float r = 0.f;
#pragma unroll
        for (int w = 0; w < 8; w++) r += s_scale[w] * s_r[w][tid];
        r *= inv_s;
        g_qstar[b * 128 + tid]      = g_hl[b * 64 + tid];
        g_qstar[b * 128 + 64 + tid] = r;
    }
}

__global__ void k_final(const float* __restrict__ W1, const float* __restrict__ b1,
                        const float* __restrict__ W2, const float* __restrict__ b2,
                        float* __restrict__ y) {
    int b = blockIdx.x, t = threadIdx.x;  // 64 threads
    __shared__ float qs[128];
    __shared__ float hid[64];
    qs[t]      = g_qstar[b * 128 + t];
    qs[t + 64] = g_qstar[b * 128 + 64 + t];
    __syncthreads();
    float acc = b1[t];
#pragma unroll 8
    for (int k = 0; k < 128; k++) acc += qs[k] * W1[k * 64 + t];
    hid[t] = fmaxf(acc, 0.f);
    __syncthreads();
    if (t < 12) {
        float a = b2[t];
#pragma unroll 8
        for (int k = 0; k < 64; k++) a += hid[k] * W2[k * 12 + t];
        y[b * 12 + t] = a;
    }
}

// ---------------- launch ----------------
extern "C" void kernel_launch(void* const* d_in, const int* in_sizes, int n_in,
                              void* d_out, int out_size) {
    const float* x     = (const float*)d_in[0];
    const int*   ei    = (const int*)  d_in[1];
    const int*   batch = (const int*)  d_in[2];
    const float* W0    = (const float*)d_in[3];
    const float* b0    = (const float*)d_in[4];
    const float* Wc    = (const float*)d_in[5];
    const float* bc    = (const float*)d_in[6];
    const float* Wih   = (const float*)d_in[7];
    const float* Whh   = (const float*)d_in[8];
    const float* bih   = (const float*)d_in[9];
    const float* bhh   = (const float*)d_in[10];
    const float* W1    = (const float*)d_in[11];
    const float* b1    = (const float*)d_in[12];
    const float* W2    = (const float*)d_in[13];
    const float* b2    = (const float*)d_in[14];
    float* y = (float*)d_out;

    int N = in_sizes[0] / 15;
    int E = in_sizes[1] / 2;
    int B = out_size / 12;

    // ---- init + build ----
    int zmax = (N > B * 2 * D) ? N : B * 2 * D;
    k_zero<<<(zmax + 255) / 256, 256>>>(N, B, Wc);
    k_build<<<(E + 255) / 256, 256>>>(ei, E);
    k_s2sprep<<<(N + 255) / 256, 256>>>(batch, N, Wih, Whh, bih, bhh);
    k_init_feat<<<(N + 7) / 8, 256>>>(x, W0, b0, N);

    // ---- 6 fused propagation steps ----
    for (int s = 0; s < 6; s++) {
        k_prop<<<(N + 63) / 64, 256>>>(bc, N, s & 1, (s == 5) ? 1 : 0);
    }

    // ---- Set2Set: 6 x (gates, attn) ----
    for (int s = 0; s < 6; s++) {
        k_gates<<<(B + 7) / 8, 256>>>(B);
        k_attn<<<B, 256>>>(N);
    }

    // ---- final MLP ----
    k_final<<<B, 64>>>(W1, b1, W2, b2, y);
}

// round 17
// speedup vs baseline: 1.1720x; 1.0622x over previous
#include <cuda_runtime.h>
#include <cuda_fp16.h>
#include <stdint.h>
#include <math.h>

#define D      64
#define CAP    128           // max in-degree slots (Poisson(32): P(>=128) ~ e^-81)
#define MAXN   100000
#define MAXB   1024

// ---------------- static device scratch ----------------
__device__ __half2 g_h0[(MAXN + 1) * 32];  // fp16 node features (scaled by dinv), ping
__device__ __half2 g_h1[(MAXN + 1) * 32];  // pong
__device__ int     g_cnt[MAXN];
__device__ int     g_csr_row[MAXN * CAP];
__device__ float   g_dinv[MAXN];
__device__ int     g_start[MAXB];
__device__ int     g_gcnt[MAXB];
__device__ __half  g_wT16[192 * 256];     // transposed [Wih|Whh] fp16: wT[k][out]
__device__ float   g_bsum[256];           // bih + bhh
__device__ __half  g_wc16[64 * 64];       // Wc in fp16, row-major [k][n]

__device__ __forceinline__ float sigmoidf(float x) { return 1.0f / (1.0f + expf(-x)); }

#define LDSM_X4(r0,r1,r2,r3, addr) \
  asm volatile("ldmatrix.sync.aligned.m8n8.x4.shared.b16 {%0,%1,%2,%3}, [%4];" \
    : "=r"(r0), "=r"(r1), "=r"(r2), "=r"(r3) : "r"(addr))

#define LDSM_X4_T(r0,r1,r2,r3, addr) \
  asm volatile("ldmatrix.sync.aligned.m8n8.x4.trans.shared.b16 {%0,%1,%2,%3}, [%4];" \
    : "=r"(r0), "=r"(r1), "=r"(r2), "=r"(r3) : "r"(addr))

#define MMA16816(c0,c1,c2,c3, a0,a1,a2,a3, b0,b1) \
  asm volatile("mma.sync.aligned.m16n8k16.row.col.f32.f16.f16.f32 " \
    "{%0,%1,%2,%3}, {%4,%5,%6,%7}, {%8,%9}, {%0,%1,%2,%3};" \
    : "+f"(c0), "+f"(c1), "+f"(c2), "+f"(c3) \
    : "r"(a0), "r"(a1), "r"(a2), "r"(a3), "r"(b0), "r"(b1))

// ---------------- init / build ----------------
__global__ void k_zero(int N, int B, const float* __restrict__ Wc) {
    int i = blockIdx.x * blockDim.x + threadIdx.x;
    if (i < N) g_cnt[i] = 0;
    if (i < B) { g_start[i] = N; g_gcnt[i] = 0; }
    if (i < 64 * 64) g_wc16[i] = __float2half(Wc[i]);
    if (i < 32) {
        __half2 z = __floats2half2_rn(0.f, 0.f);
        g_h0[MAXN * 32 + i] = z;
        g_h1[MAXN * 32 + i] = z;
    }
}

__global__ void k_build(const int* __restrict__ ei, int E) {
    int e = blockIdx.x * blockDim.x + threadIdx.x;
    if (e >= E) return;
    int r = ei[e];
    int c = ei[E + e];
    int slot = atomicAdd(&g_cnt[c], 1);
    if (slot < CAP) g_csr_row[c * CAP + slot] = r;
}

// merged: dinv + graph boundaries/counts + LSTM weight transpose (fp16)
__global__ void k_s2sprep(const int* __restrict__ batch, int N,
                          const float* __restrict__ Wih, const float* __restrict__ Whh,
                          const float* __restrict__ bih, const float* __restrict__ bhh) {
    int i = blockIdx.x * blockDim.x + threadIdx.x;
    if (i < N) {
        float deg = (float)(g_cnt[i] + 1);
        g_dinv[i] = rsqrtf(deg);
        int bn = batch[i];
        if (i == 0 || batch[i - 1] != bn) g_start[bn] = i;
        atomicAdd(&g_gcnt[bn], 1);
    }
    if (i < 192 * 256) {
        int k = i >> 8, o = i & 255;
        float v = (k < 128) ? Wih[o * 128 + k] : Whh[o * 64 + (k - 128)];
        g_wT16[k * 256 + o] = __float2half(v);
        if (k == 0) g_bsum[o] = bih[o] + bhh[o];
    }
}

// out0 = dinv * relu(x @ W0 + b0) -> fp16 ping buffer; smem-staged, 8 nodes/block
__global__ void k_init_feat(const float* __restrict__ x, const float* __restrict__ W0,
                            const float* __restrict__ b0, int N) {
    __shared__ float w0s[15][64];
    __shared__ float b0s[64];
    __shared__ float xrs[8][16];
    int t = threadIdx.x;
    int nb = blockIdx.x * 8;

    if (t < 64) b0s[t] = b0[t];
    for (int i = t; i < 15 * 64; i += 256) w0s[i >> 6][i & 63] = W0[i];
    if (t < 120) {
        int ln = t / 15, lf = t % 15;
        int n = nb + ln;
        xrs[ln][lf] = (n < N) ? x[n * 15 + lf] : 0.f;
    }
    __syncthreads();

    int ln = t >> 5, p = t & 31;
    int n = nb + ln;
    if (n >= N) return;
    int c0 = 2 * p;
    float a0 = b0s[c0], a1 = b0s[c0 + 1];
#pragma unroll
    for (int k = 0; k < 15; k++) {
        float xv = xrs[ln][k];
        a0 += xv * w0s[k][c0];
        a1 += xv * w0s[k][c0 + 1];
    }
    float dv = g_dinv[n];
    g_h0[(size_t)n * 32 + p] = __floats2half2_rn(dv * fmaxf(a0, 0.f), dv * fmaxf(a1, 0.f));
}

// ---------------- fused propagation (R14's validated 8-wide form) ----------------
__global__ void k_prop(const float* __restrict__ bc, int N, int flip, int last) {
    const __half2* __restrict__ src = flip ? g_h1 : g_h0;
    __half2*       __restrict__ dst = flip ? g_h0 : g_h1;
    __shared__ __half xs_h[64][72];
    __shared__ __half ws_h[64][72];
    __shared__ float  bcs[64];
    int t = threadIdx.x;               // 256 threads
    int base = blockIdx.x * 64;
    int wrp = t >> 5, lane = t & 31;

    if (t < 64) bcs[t] = bc[t];
    {
        const uint4* wsrc = (const uint4*)g_wc16;
#pragma unroll
        for (int i = t; i < 512; i += 256) {
            int row = i >> 3, c8 = (i & 7) << 3;
            *(uint4*)&ws_h[row][c8] = wsrc[i];
        }
    }

#pragma unroll 1
    for (int q = 0; q < 8; q++) {
        int row = wrp * 8 + q;
        int n = base + row;
        float ax = 0.f, ay = 0.f;
        if (n < N) {
            int cnt = g_cnt[n]; if (cnt > CAP) cnt = CAP;
            const int* rows = &g_csr_row[n * CAP];
            int s8 = cnt & ~7;
            if (s8) {
                int4 ra = *(const int4*)(rows);
                int4 rb = *(const int4*)(rows + 4);
                for (int s = 8; ; s += 8) {
                    int4 ra_n, rb_n;
                    if (s < s8) {
                        ra_n = *(const int4*)(rows + s);
                        rb_n = *(const int4*)(rows + s + 4);
                    }
                    __half2 h0 = src[ra.x * 32 + lane];
                    __half2 h1 = src[ra.y * 32 + lane];
                    __half2 h2 = src[ra.z * 32 + lane];
                    __half2 h3 = src[ra.w * 32 + lane];
                    __half2 h4 = src[rb.x * 32 + lane];
                    __half2 h5 = src[rb.y * 32 + lane];
                    __half2 h6 = src[rb.z * 32 + lane];
                    __half2 h7 = src[rb.w * 32 + lane];
                    __half2 t0 = __hadd2(h0, h1);
                    __half2 t1 = __hadd2(h2, h3);
                    __half2 t2 = __hadd2(h4, h5);
                    __half2 t3 = __hadd2(h6, h7);
                    t0 = __hadd2(t0, t1);
                    t2 = __hadd2(t2, t3);
                    t0 = __hadd2(t0, t2);
                    float2 f = __half22float2(t0);
                    ax += f.x; ay += f.y;
                    if (s >= s8) break;
                    ra = ra_n; rb = rb_n;
                }
            }
            int s = s8;
            if (s + 4 <= cnt) {
                int4 ra = *(const int4*)(rows + s);
                __half2 h0 = src[ra.x * 32 + lane];
                __half2 h1 = src[ra.y * 32 + lane];
                __half2 h2 = src[ra.z * 32 + lane];
                __half2 h3 = src[ra.w * 32 + lane];
                __half2 t0 = __hadd2(__hadd2(h0, h1), __hadd2(h2, h3));
                float2 f = __half22float2(t0);
                ax += f.x; ay += f.y;
                s += 4;
            }
            for (; s < cnt; s++) {
                float2 f = __half22float2(src[rows[s] * 32 + lane]);
                ax += f.x; ay += f.y;
            }
            float2 hs = __half22float2(src[n * 32 + lane]);
            float dv = g_dinv[n];
            ax = dv * (ax + hs.x);
            ay = dv * (ay + hs.y);
        }
        *(__half2*)&xs_h[row][lane * 2] = __floats2half2_rn(ax, ay);
    }
    __syncthreads();

    int wr = wrp >> 1;
    int wc = wrp & 1;
    int g  = lane >> 2;
    int tt = lane & 3;

    float c[4][4];
#pragma unroll
    for (int i = 0; i < 4; i++)
#pragma unroll
        for (int j = 0; j < 4; j++) c[i][j] = 0.f;

    int arow = wr * 16 + ((lane >> 3) & 1) * 8 + (lane & 7);
    int asub = (lane >> 4) * 8;
    int brsub = ((lane >> 3) & 1) * 8 + (lane & 7);
    int bcsub = (lane >> 4) * 8;

#pragma unroll
    for (int kk = 0; kk < 4; kk++) {
        uint32_t a0, a1, a2, a3;
        uint32_t aaddr = (uint32_t)__cvta_generic_to_shared(&xs_h[arow][kk * 16 + asub]);
        LDSM_X4(a0, a1, a2, a3, aaddr);
#pragma unroll
        for (int hn = 0; hn < 2; hn++) {
            uint32_t bb0, bb1, bb2, bb3;
            uint32_t baddr = (uint32_t)__cvta_generic_to_shared(
                &ws_h[kk * 16 + brsub][wc * 32 + hn * 16 + bcsub]);
            LDSM_X4_T(bb0, bb1, bb2, bb3, baddr);
            MMA16816(c[hn*2][0], c[hn*2][1], c[hn*2][2], c[hn*2][3],
                     a0, a1, a2, a3, bb0, bb1);
            MMA16816(c[hn*2+1][0], c[hn*2+1][1], c[hn*2+1][2], c[hn*2+1][3],
                     a0, a1, a2, a3, bb2, bb3);
        }
    }

    int r0 = base + wr * 16 + g;
    int r1 = r0 + 8;
    float sc0 = 1.f, sc1 = 1.f;
    if (!last) {
        if (r0 < N) sc0 = g_dinv[r0];
        if (r1 < N) sc1 = g_dinv[r1];
    }
#pragma unroll
    for (int ns = 0; ns < 4; ns++) {
        int col = wc * 32 + ns * 8 + 2 * tt;
        float bx = bcs[col], by = bcs[col + 1];
        if (r0 < N) {
            float vx = fmaxf(c[ns][0] + bx, 0.f) * sc0;
            float vy = fmaxf(c[ns][1] + by, 0.f) * sc0;
            dst[(size_t)r0 * 32 + (col >> 1)] = __floats2half2_rn(vx, vy);
        }
        if (r1 < N) {
            float vx = fmaxf(c[ns][2] + bx, 0.f) * sc1;
            float vy = fmaxf(c[ns][3] + by, 0.f) * sc1;
            dst[(size_t)r1 * 32 + (col >> 1)] = __floats2half2_rn(vx, vy);
        }
    }
}

// ---------------- fused Set2Set: one block per graph, all 6 iterations + final MLP ----
// dynamic smem layout:
//   [0, 98304)          fp16 weights wT16[192][256]
//   then floats: xk[192] (q_star[0..127], h_l at [128..191]), cl[64],
//                gate[256], s_r[8][64], s_m[8], s_ls[8], s_sc[8], inv_s, hid[64]
__global__ void k_set2set(const float* __restrict__ W1, const float* __restrict__ b1,
                          const float* __restrict__ W2, const float* __restrict__ b2,
                          float* __restrict__ y) {
    extern __shared__ char sm[];
    __half* w16s = (__half*)sm;
    float* fbase = (float*)(sm + 192 * 256 * 2);
    float* xk   = fbase;            // 192
    float* cl   = xk + 192;         // 64
    float* gate = cl + 64;          // 256
    float* s_r  = gate + 256;       // 512 (8x64)
    float* s_m  = s_r + 512;        // 8
    float* s_ls = s_m + 8;          // 8
    float* s_sc = s_ls + 8;         // 8
    float* inv_s = s_sc + 8;        // 1
    float* hid  = inv_s + 1;        // 64

    int b = blockIdx.x, tid = threadIdx.x;
    int wrp = tid >> 5, lane = tid & 31;
    int st = g_start[b];
    int cnt = g_gcnt[b];

    // load LSTM weights into smem once (6144 uint4)
    {
        const uint4* wsrc = (const uint4*)g_wT16;
        uint4* wdst = (uint4*)w16s;
#pragma unroll
        for (int i = tid; i < 6144; i += 256) wdst[i] = wsrc[i];
    }
    if (tid < 192) xk[tid] = 0.f;
    if (tid < 64) cl[tid] = 0.f;
    float bsum = g_bsum[tid];
    __syncthreads();

    for (int it = 0; it < 6; it++) {
        // ---- LSTM gates: thread tid computes output row tid ----
        float acc = bsum;
#pragma unroll 8
        for (int k = 0; k < 192; k++)
            acc += xk[k] * __half2float(w16s[k * 256 + tid]);
        gate[tid] = acc;
        __syncthreads();
        if (tid < 64) {
            float ig = sigmoidf(gate[tid]);
            float fg = sigmoidf(gate[64 + tid]);
            float gv = tanhf   (gate[128 + tid]);
            float og = sigmoidf(gate[192 + tid]);
            float cv = fg * cl[tid] + ig * gv;
            cl[tid] = cv;
            float hv = og * tanhf(cv);
            xk[tid] = hv;        // q part of q_star
            xk[128 + tid] = hv;  // h_l
        }
        __syncthreads();

        // ---- attention: online softmax over this graph's nodes ----
        float2 qv = make_float2(xk[128 + lane * 2], xk[128 + lane * 2 + 1]);
        float m_w = -INFINITY, ls_w = 0.f;
        float rx = 0.f, ry = 0.f;
        for (int i = wrp; i < cnt; i += 8) {
            int n = st + i;
            float2 ov = __half22float2(g_h0[(size_t)n * 32 + lane]);
            float s = ov.x * qv.x + ov.y * qv.y;
#pragma unroll
            for (int o = 16; o; o >>= 1) s += __shfl_xor_sync(0xffffffffu, s, o);
            float m_new = fmaxf(m_w, s);
            float scale = expf(m_w - m_new);
            float a = expf(s - m_new);
            ls_w = ls_w * scale + a;
            rx = rx * scale + a * ov.x;
            ry = ry * scale + a * ov.y;
            m_w = m_new;
        }
        s_r[wrp * 64 + lane * 2]     = rx;
        s_r[wrp * 64 + lane * 2 + 1] = ry;
        if (lane == 0) { s_m[wrp] = m_w; s_ls[wrp] = ls_w; }
        __syncthreads();

        if (tid < 8) {
            float mv = s_m[tid];
            float M = mv;
#pragma unroll
            for (int o = 4; o; o >>= 1) M = fmaxf(M, __shfl_xor_sync(0xffu, M, o));
            float sc = (mv > -INFINITY) ? expf(mv - M) : 0.f;
            s_sc[tid] = sc;
            float l = s_ls[tid] * sc;
#pragma unroll
            for (int o = 4; o; o >>= 1) l += __shfl_xor_sync(0xffu, l, o);
            if (tid == 0) *inv_s = (l > 0.f) ? (1.0f / l) : 0.f;
        }
        __syncthreads();

        if (tid < 64) {
            float r = 0.f;
#pragma unroll
            for (int w = 0; w < 8; w++) r += s_sc[w] * s_r[w * 64 + tid];
            xk[64 + tid] = r * (*inv_s);
        }
        __syncthreads();
    }

    // ---- final MLP: y = relu(q_star @ W1 + b1) @ W2 + b2 ----
    if (tid < 64) {
        float acc = b1[tid];
#pragma unroll 8
        for (int k = 0; k < 128; k++) acc += xk[k] * W1[k * 64 + tid];
        hid[tid] = fmaxf(acc, 0.f);
    }
    __syncthreads();
    if (tid < 12) {
        float a = b2[tid];
#pragma unroll 8
        for (int k = 0; k < 64; k++) a += hid[k] * W2[k * 12 + tid];
        y[b * 12 + tid] = a;
    }
}

// ---------------- launch ----------------
extern "C" void kernel_launch(void* const* d_in, const int* in_sizes, int n_in,
                              void* d_out, int out_size) {
    const float* x     = (const float*)d_in[0];
    const int*   ei    = (const int*)  d_in[1];
    const int*   batch = (const int*)  d_in[2];
    const float* W0    = (const float*)d_in[3];
    const float* b0    = (const float*)d_in[4];
    const float* Wc    = (const float*)d_in[5];
    const float* bc    = (const float*)d_in[6];
    const float* Wih   = (const float*)d_in[7];
    const float* Whh   = (const float*)d_in[8];
    const float* bih   = (const float*)d_in[9];
    const float* bhh   = (const float*)d_in[10];
    const float* W1    = (const float*)d_in[11];
    const float* b1    = (const float*)d_in[12];
    const float* W2    = (const float*)d_in[13];
    const float* b2    = (const float*)d_in[14];
    float* y = (float*)d_out;

    int N = in_sizes[0] / 15;
    int E = in_sizes[1] / 2;
    int B = out_size / 12;

    // dynamic smem for k_set2set: 98304 (fp16 weights) + 1113 floats
    int s2s_smem = 192 * 256 * 2 + (192 + 64 + 256 + 512 + 8 + 8 + 8 + 1 + 64) * 4;
    cudaFuncSetAttribute(k_set2set, cudaFuncAttributeMaxDynamicSharedMemorySize, s2s_smem);

    // ---- init + build ----
    int zmax = (N > 64 * 64) ? N : 64 * 64;
    k_zero<<<(zmax + 255) / 256, 256>>>(N, B, Wc);
    k_build<<<(E + 255) / 256, 256>>>(ei, E);
    k_s2sprep<<<(N + 255) / 256, 256>>>(batch, N, Wih, Whh, bih, bhh);
    k_init_feat<<<(N + 7) / 8, 256>>>(x, W0, b0, N);

    // ---- 6 fused propagation steps ----
    for (int s = 0; s < 6; s++) {
        k_prop<<<(N + 63) / 64, 256>>>(bc, N, s & 1, (s == 5) ? 1 : 0);
    }

    // ---- fused Set2Set (all 6 iterations) + final MLP ----
    k_set2set<<<B, 256, s2s_smem>>>(W1, b1, W2, b2, y);
}